// round 10
// baseline (speedup 1.0000x reference)
#include <cuda_runtime.h>
#include <cstdint>

// Problem constants
#define BATCHN 128
#define GS 7
#define NB 2
#define NC 20
#define CH 30
#define CELLS (BATCHN * GS * GS)      // 6272
#define NTOT (CELLS * NB)             // 12544
#define PER_BATCH (GS * GS * NB)      // 98
#define THR_NMS 0.3f

// rank kernel: 256-thread blocks; 16 elements/block; warps 0-3 stream half 0,
// warps 4-7 stream half 1 (4 elements per warp each)
#define RWB 256
#define EPB 16
#define NVBLK (NTOT / EPB)            // 784 valid blocks (worst case V = NTOT)
#define NIBLK (NTOT / RWB)            // 49 invalid blocks

#define HASHBITS 17
#define HASHSZ (1 << HASHBITS)        // 131072 buckets

typedef unsigned long long u64;

// ---------------- device scratch (static; no cudaMalloc) ---------------------
__device__ __align__(16) u64 g_vkeys[NTOT];      // compacted valid keys
__device__ __align__(16) unsigned g_vhi[NTOT];   // hi 32 bits of each valid key
__device__ float4 g_box[NTOT];
__device__ float4 g_pay[NTOT];        // (score, label, keep, 0)
__device__ int g_cnt[BATCHN];         // valid count per batch
__device__ u64 g_vmask[BATCHN * 2];   // validity bitmask per batch (98 bits)
// [0] = vtotal counter, [1..HASHSZ] = tie-detect hash table; one memset zeroes all
__device__ unsigned g_zero_region[1 + HASHSZ];

// sigmoid matching XLA-GPU exp-based logistic: 1/(1+__nv_expf(-x)), div.rn
__device__ __forceinline__ float sigmoidf(float x) {
    return 1.0f / (1.0f + expf(-x));
}

__device__ __forceinline__ unsigned f2sortable(float f) {
    unsigned b = __float_as_uint(f);
    return (b & 0x80000000u) ? ~b : (b | 0x80000000u);
}

__device__ __forceinline__ unsigned tie_hash(unsigned hi) {
    return (hi * 2654435761u) >> (32 - HASHBITS);
}

// ============ A) fused decode + parallel local rank + NMS + compaction =======
__global__ void __launch_bounds__(256) decode_nms_kernel(const float* __restrict__ p) {
    __shared__ float s_dec[GS * GS * CH];        // 1470 decoded values
    __shared__ u64 s_key[PER_BATCH];
    __shared__ float4 s_nbox[PER_BATCH];
    __shared__ unsigned char s_nlab[PER_BATCH];
    __shared__ unsigned char s_nloc[PER_BATCH];
    __shared__ unsigned char s_keep[PER_BATCH];
    __shared__ __align__(16) unsigned s_adj[PER_BATCH][4];  // suppression rows
    __shared__ unsigned s_supw[4];
    __shared__ unsigned s_wb[4];
    __shared__ int s_cnt;
    __shared__ int s_base;

    int tid = threadIdx.x;
    int b = blockIdx.x;

    // Phase 0: cooperative sigmoid decode (w,h channels raw)
    const float* pb = p + (size_t)b * (GS * GS * CH);
    for (int i = tid; i < GS * GS * CH; i += 256) {
        int c = i % CH;
        float x = pb[i];
        bool raw = (c == 2) | (c == 3) | (c == 6) | (c == 7);
        s_dec[i] = raw ? x : sigmoidf(x);
    }
    if (tid < PER_BATCH) {
        s_adj[tid][0] = 0; s_adj[tid][1] = 0; s_adj[tid][2] = 0; s_adj[tid][3] = 0;
        s_keep[tid] = 0;
    }
    __syncthreads();

    // Phase 1: per-box decode (one thread per box)
    bool valid = false;
    u64 mykey = 0;
    float4 mybox;
    float myconf = 0.0f;
    unsigned char mylab = 0;
    if (tid < PER_BATCH) {
        int cell = tid >> 1;
        int bb = tid & 1;
        int gy = cell / GS, gx = cell % GS;
        const float* d = s_dec + cell * CH;

        float best = d[8 + NB + 0];
        int bi = 0;
#pragma unroll
        for (int c = 1; c < NC; c++) {
            float v = d[8 + NB + c];
            if (v > best) { best = v; bi = c; }
        }
        mylab = (unsigned char)(bi + 1);

        myconf = d[8 + bb];
        valid = myconf > 0.5f;
        float sx = d[bb * 4 + 0];
        float sy = d[bb * 4 + 1];
        float w = d[bb * 4 + 2];
        float h = d[bb * 4 + 3];
        float cx = (sx + (float)gx) / 7.0f;
        float cy = (sy + (float)gy) / 7.0f;
        mybox.x = cx - w / 2.0f;
        mybox.y = cy - h / 2.0f;
        mybox.z = cx + w / 2.0f;
        mybox.w = cy + h / 2.0f;

        int n = b * PER_BATCH + tid;
        g_box[n] = mybox;
        float keyf = valid ? myconf : __int_as_float(0xff800000);   // -inf
        mykey = ((u64)f2sortable(keyf) << 32) | (unsigned)n;
        s_key[tid] = mykey;
    }
    unsigned wb = __ballot_sync(0xffffffffu, valid);
    if ((tid & 31) == 0 && tid < 128) s_wb[tid >> 5] = wb;
    __syncthreads();
    if (tid == 0) {
        u64 m0 = (u64)s_wb[0] | ((u64)s_wb[1] << 32);
        u64 m1 = (u64)s_wb[2] | ((u64)s_wb[3] << 32);
        g_vmask[2 * b] = m0;
        g_vmask[2 * b + 1] = m1;
        int cnt = __popcll(m0) + __popcll(m1);
        s_cnt = cnt;
        g_cnt[b] = cnt;
        s_base = (int)atomicAdd(&g_zero_region[0], (unsigned)cnt);
    }
    __syncthreads();

    // Phase 2: parallel local rank (valid keys outrank all invalid; keys unique)
    if (tid < PER_BATCH && valid) {
        int r = 0;
#pragma unroll 7
        for (int j = 0; j < PER_BATCH; j++)
            r += (s_key[j] > mykey);
        s_nbox[r] = mybox;
        s_nlab[r] = mylab;
        s_nloc[r] = (unsigned char)tid;
        g_vkeys[s_base + r] = mykey;
        unsigned hi = (unsigned)(mykey >> 32);
        g_vhi[s_base + r] = hi;
        atomicAdd(&g_zero_region[1 + tie_hash(hi)], 1u);   // tie pre-filter
    }
    __syncthreads();

    int cnt = s_cnt;

    // Phase 3: flattened triangular pairwise IoU -> adjacency bits
    {
        int P = cnt * (cnt - 1) / 2;
        for (int pp = tid; pp < P; pp += 256) {
            int s = P - 1 - pp;
            int k = (int)floorf((sqrtf(8.0f * (float)s + 1.0f) - 1.0f) * 0.5f);
            while ((k + 1) * (k + 2) / 2 <= s) k++;
            while (k * (k + 1) / 2 > s) k--;
            int o = s - k * (k + 1) / 2;
            int i = cnt - 2 - k;
            int j = cnt - 1 - o;
            if (s_nlab[i] == s_nlab[j]) {
                float4 bi = s_nbox[i];
                float4 bj = s_nbox[j];
                float ltx = fmaxf(bi.x, bj.x);
                float lty = fmaxf(bi.y, bj.y);
                float rbx = fminf(bi.z, bj.z);
                float rby = fminf(bi.w, bj.w);
                float iw = fmaxf(rbx - ltx, 0.0f);
                float ih = fmaxf(rby - lty, 0.0f);
                float inter = iw * ih;
                float ai = (bi.z - bi.x) * (bi.w - bi.y);
                float aj = (bj.z - bj.x) * (bj.w - bj.y);
                float uni = ai + aj - inter;
                float iou = inter / fmaxf(uni, 1e-9f);
                if (iou > THR_NMS)
                    atomicOr(&s_adj[i][j >> 5], 1u << (j & 31));
            }
        }
    }
    __syncthreads();

    // Phase 4: greedy scan, warp-parallel, branch-free mask accumulation
    if (tid < 32) {
        int lane = tid;
        unsigned r00 = s_adj[lane][0],      r01 = s_adj[lane][1];
        unsigned r02 = s_adj[lane][2],      r03 = s_adj[lane][3];
        unsigned r10 = s_adj[lane + 32][0], r11 = s_adj[lane + 32][1];
        unsigned r12 = s_adj[lane + 32][2], r13 = s_adj[lane + 32][3];
        unsigned r20 = s_adj[lane + 64][0], r21 = s_adj[lane + 64][1];
        unsigned r22 = s_adj[lane + 64][2], r23 = s_adj[lane + 64][3];
        unsigned r30 = 0, r31 = 0, r32 = 0, r33 = 0;
        if (lane < 2) {
            r30 = s_adj[lane + 96][0]; r31 = s_adj[lane + 96][1];
            r32 = s_adj[lane + 96][2]; r33 = s_adj[lane + 96][3];
        }

        unsigned sup0 = 0, sup1 = 0, sup2 = 0, sup3 = 0;
        int c = cnt;
        int e0 = min(c, 32);
        for (int s = 0; s < e0; s++) {
            unsigned m = ((sup0 >> s) & 1u) - 1u;      // ~0 if kept, 0 if suppressed
            sup0 |= __shfl_sync(0xffffffffu, r00, s) & m;
            sup1 |= __shfl_sync(0xffffffffu, r01, s) & m;
            sup2 |= __shfl_sync(0xffffffffu, r02, s) & m;
            sup3 |= __shfl_sync(0xffffffffu, r03, s) & m;
        }
        int e1 = min(c - 32, 32);
        for (int s = 0; s < e1; s++) {
            unsigned m = ((sup1 >> s) & 1u) - 1u;
            sup0 |= __shfl_sync(0xffffffffu, r10, s) & m;
            sup1 |= __shfl_sync(0xffffffffu, r11, s) & m;
            sup2 |= __shfl_sync(0xffffffffu, r12, s) & m;
            sup3 |= __shfl_sync(0xffffffffu, r13, s) & m;
        }
        int e2 = min(c - 64, 32);
        for (int s = 0; s < e2; s++) {
            unsigned m = ((sup2 >> s) & 1u) - 1u;
            sup0 |= __shfl_sync(0xffffffffu, r20, s) & m;
            sup1 |= __shfl_sync(0xffffffffu, r21, s) & m;
            sup2 |= __shfl_sync(0xffffffffu, r22, s) & m;
            sup3 |= __shfl_sync(0xffffffffu, r23, s) & m;
        }
        int e3 = min(c - 96, 32);
        for (int s = 0; s < e3; s++) {
            unsigned m = ((sup3 >> s) & 1u) - 1u;
            sup0 |= __shfl_sync(0xffffffffu, r30, s) & m;
            sup1 |= __shfl_sync(0xffffffffu, r31, s) & m;
            sup2 |= __shfl_sync(0xffffffffu, r32, s) & m;
            sup3 |= __shfl_sync(0xffffffffu, r33, s) & m;
        }
        if (lane == 0) {
            s_supw[0] = sup0; s_supw[1] = sup1; s_supw[2] = sup2; s_supw[3] = sup3;
        }
    }
    __syncthreads();

    if (tid < cnt) {
        if (!((s_supw[tid >> 5] >> (tid & 31)) & 1u))
            s_keep[s_nloc[tid]] = 1;
    }
    __syncthreads();

    // Phase 5: payload write
    if (tid < PER_BATCH) {
        int n = b * PER_BATCH + tid;
        g_pay[n] = make_float4(myconf, (float)mylab,
                               s_keep[tid] ? 1.0f : 0.0f, 0.0f);
    }
}

// ============ B) fused valid-rank + invalid-write ============================
__device__ __forceinline__ void write_valid_row(float* out, u64 mykey, int rank) {
    unsigned idx = (unsigned)(mykey & 0xffffffffu);
    float4 bx = g_box[idx];
    float4 pay = g_pay[idx];
    out[rank] = (float)(idx / PER_BATCH);
    *(float4*)(out + NTOT + 4 * rank) = bx;
    out[5 * NTOT + rank] = pay.y;   // label
    out[6 * NTOT + rank] = pay.x;   // score
    out[7 * NTOT + rank] = pay.z;   // keep
}

__global__ void __launch_bounds__(RWB) rank_write_kernel(float* __restrict__ out) {
    int blk = blockIdx.x;
    int tid = threadIdx.x;

    if (blk < NVBLK) {
        int V = (int)g_zero_region[0];
        int eBase = blk * EPB;
        if (eBase >= V) return;
        int wid = tid >> 5;
        int lane = tid & 31;
        int half = wid >> 2;               // 0 or 1
        int quad = wid & 3;                // element group within block
        int e0 = eBase + quad * 4;

        __shared__ int s_part[2][EPB];
        __shared__ unsigned char s_slow[EPB];

        unsigned mh0 = g_vhi[min(e0 + 0, V - 1)];
        unsigned mh1 = g_vhi[min(e0 + 1, V - 1)];
        unsigned mh2 = g_vhi[min(e0 + 2, V - 1)];
        unsigned mh3 = g_vhi[min(e0 + 3, V - 1)];

        int nv4 = V >> 2;                  // full uint4 count
        int h0 = nv4 >> 1;                 // split point
        int lo = half ? h0 : 0;
        int he = half ? nv4 : h0;

        int c0 = 0, c1 = 0, c2 = 0, c3 = 0;
        const uint4* vh4 = (const uint4*)g_vhi;
#pragma unroll 4
        for (int i4 = lo + lane; i4 < he; i4 += 32) {
            uint4 v = vh4[i4];
            c0 += (v.x > mh0) + (v.y > mh0) + (v.z > mh0) + (v.w > mh0);
            c1 += (v.x > mh1) + (v.y > mh1) + (v.z > mh1) + (v.w > mh1);
            c2 += (v.x > mh2) + (v.y > mh2) + (v.z > mh2) + (v.w > mh2);
            c3 += (v.x > mh3) + (v.y > mh3) + (v.z > mh3) + (v.w > mh3);
        }
        if (half == 1) {                   // scalar tail keys [nv4*4, V)
            for (int t = nv4 * 4 + lane; t < V; t += 32) {
                unsigned v = g_vhi[t];
                c0 += (v > mh0); c1 += (v > mh1); c2 += (v > mh2); c3 += (v > mh3);
            }
        }
#pragma unroll
        for (int d = 16; d >= 1; d >>= 1) {
            c0 += __shfl_xor_sync(0xffffffffu, c0, d);
            c1 += __shfl_xor_sync(0xffffffffu, c1, d);
            c2 += __shfl_xor_sync(0xffffffffu, c2, d);
            c3 += __shfl_xor_sync(0xffffffffu, c3, d);
        }
        if (lane == 0) {
            s_part[half][quad * 4 + 0] = c0;
            s_part[half][quad * 4 + 1] = c1;
            s_part[half][quad * 4 + 2] = c2;
            s_part[half][quad * 4 + 3] = c3;
        }
        __syncthreads();

        // fast-path write for elements with a unique hi word; defer ties
        if (tid < EPB) {
            bool slow = false;
            if (eBase + tid < V) {
                unsigned myhi = g_vhi[eBase + tid];
                slow = (g_zero_region[1 + tie_hash(myhi)] >= 2u);
                if (!slow) {
                    int rank = s_part[0][tid] + s_part[1][tid];
                    write_valid_row(out, g_vkeys[eBase + tid], rank);
                }
            }
            s_slow[tid] = slow ? 1 : 0;
        }
        __syncthreads();

        // slow path: exact 64-bit rank for tie candidates (warp 0)
        if (tid < 32) {
            for (int t = 0; t < EPB; t++) {
                if (!s_slow[t]) continue;
                u64 key = g_vkeys[eBase + t];
                int c = 0;
                for (int i = tid; i < V; i += 32)
                    c += (g_vkeys[i] > key);
#pragma unroll
                for (int d = 16; d >= 1; d >>= 1)
                    c += __shfl_xor_sync(0xffffffffu, c, d);
                if (tid == 0)
                    write_valid_row(out, key, c);
            }
        }
    } else {
        __shared__ int s_incl[BATCHN];
        __shared__ int s_ws[4];
        int lane = tid & 31;

        if (tid < BATCHN) {
            int x = g_cnt[tid];
#pragma unroll
            for (int d = 1; d < 32; d <<= 1) {
                int y = __shfl_up_sync(0xffffffffu, x, d);
                if (lane >= d) x += y;
            }
            if (lane == 31) s_ws[tid >> 5] = x;
            s_incl[tid] = x;
        }
        __syncthreads();
        if (tid == 0) {
            int a = 0;
#pragma unroll
            for (int w = 0; w < 4; w++) { int t = s_ws[w]; s_ws[w] = a; a += t; }
        }
        __syncthreads();
        if (tid < BATCHN) s_incl[tid] += s_ws[tid >> 5];
        __syncthreads();

        int V = s_incl[BATCHN - 1];
        int n = (blk - NVBLK) * RWB + tid;   // 49*256 == NTOT exactly
        int b = n / PER_BATCH;
        int local = n - b * PER_BATCH;
        u64 m0 = g_vmask[2 * b];
        u64 m1 = g_vmask[2 * b + 1];
        bool valid = (local < 64) ? ((m0 >> local) & 1ULL)
                                  : ((m1 >> (local - 64)) & 1ULL);
        if (valid) return;

        u64 i0 = ~m0;
        u64 i1 = (~m1) & ((1ULL << (PER_BATCH - 64)) - 1);
        int after;
        if (local < 64) {
            u64 hi = (local == 63) ? 0ULL : (i0 >> (local + 1));
            after = __popcll(hi) + __popcll(i1);
        } else {
            after = __popcll(i1 >> (local - 63));
        }
        int invafter = (NTOT - V) - (PER_BATCH * (b + 1) - s_incl[b]);
        int rank = V + invafter + after;

        float4 bx = g_box[n];
        float4 pay = g_pay[n];
        out[rank] = (float)b;
        *(float4*)(out + NTOT + 4 * rank) = bx;
        out[5 * NTOT + rank] = pay.y;
        out[6 * NTOT + rank] = pay.x;
        out[7 * NTOT + rank] = 0.0f;
    }
}

// ---------------- launch -----------------------------------------------------
extern "C" void kernel_launch(void* const* d_in, const int* in_sizes, int n_in,
                              void* d_out, int out_size) {
    const float* p = (const float*)d_in[0];
    float* out = (float*)d_out;

    void* zr = nullptr;
    cudaGetSymbolAddress(&zr, g_zero_region);
    cudaMemsetAsync(zr, 0, (1 + HASHSZ) * sizeof(unsigned));

    decode_nms_kernel<<<BATCHN, 256>>>(p);
    rank_write_kernel<<<NVBLK + NIBLK, RWB>>>(out);
}

// round 11
// speedup vs baseline: 1.7238x; 1.7238x over previous
#include <cuda_runtime.h>
#include <cstdint>

// Problem constants
#define BATCHN 128
#define GS 7
#define NB 2
#define NC 20
#define CH 30
#define CELLS (BATCHN * GS * GS)      // 6272
#define NTOT (CELLS * NB)             // 12544
#define PER_BATCH (GS * GS * NB)      // 98
#define THR_NMS 0.3f

// rank kernel: 512-thread blocks, 16 warps; 16 elements/block;
// warp group q (4 warps) streams quarter q of the key array, 4 elements/warp
#define RWB 512
#define EPB 16
#define NVBLK (NTOT / EPB)            // 784 valid blocks (worst case V = NTOT)
#define NIBLK ((NTOT + RWB - 1) / RWB) // 25 invalid blocks

typedef unsigned long long u64;

// ---------------- device scratch (static; no cudaMalloc) ---------------------
__device__ __align__(16) u64 g_vkeys[NTOT];   // compacted valid keys (any order)
__device__ float4 g_box[NTOT];
__device__ float4 g_pay[NTOT];        // (score, label, keep, 0)
__device__ int g_cnt[BATCHN];         // valid count per batch
__device__ u64 g_vmask[BATCHN * 2];   // validity bitmask per batch (98 bits)
__device__ int g_vtotal;              // atomic compaction counter (memset to 0)

// sigmoid matching XLA-GPU exp-based logistic: 1/(1+__nv_expf(-x)), div.rn
__device__ __forceinline__ float sigmoidf(float x) {
    return 1.0f / (1.0f + expf(-x));
}

__device__ __forceinline__ unsigned f2sortable(float f) {
    unsigned b = __float_as_uint(f);
    return (b & 0x80000000u) ? ~b : (b | 0x80000000u);
}

// ============ A) fused decode + parallel local rank + NMS + compaction =======
__global__ void __launch_bounds__(256) decode_nms_kernel(const float* __restrict__ p) {
    __shared__ float s_dec[GS * GS * CH];        // 1470 decoded values
    __shared__ u64 s_key[PER_BATCH];
    __shared__ float4 s_nbox[PER_BATCH];
    __shared__ unsigned char s_nlab[PER_BATCH];
    __shared__ unsigned char s_nloc[PER_BATCH];
    __shared__ unsigned char s_keep[PER_BATCH];
    __shared__ __align__(16) unsigned s_adj[PER_BATCH][4];  // suppression rows
    __shared__ unsigned s_supw[4];
    __shared__ unsigned s_wb[4];
    __shared__ int s_cnt;
    __shared__ int s_base;

    int tid = threadIdx.x;
    int b = blockIdx.x;

    // Phase 0: cooperative sigmoid decode (w,h channels raw)
    const float* pb = p + (size_t)b * (GS * GS * CH);
    for (int i = tid; i < GS * GS * CH; i += 256) {
        int c = i % CH;
        float x = pb[i];
        bool raw = (c == 2) | (c == 3) | (c == 6) | (c == 7);
        s_dec[i] = raw ? x : sigmoidf(x);
    }
    if (tid < PER_BATCH) {
        s_adj[tid][0] = 0; s_adj[tid][1] = 0; s_adj[tid][2] = 0; s_adj[tid][3] = 0;
        s_keep[tid] = 0;
    }
    __syncthreads();

    // Phase 1: per-box decode (one thread per box)
    bool valid = false;
    u64 mykey = 0;
    float4 mybox;
    float myconf = 0.0f;
    unsigned char mylab = 0;
    if (tid < PER_BATCH) {
        int cell = tid >> 1;
        int bb = tid & 1;
        int gy = cell / GS, gx = cell % GS;
        const float* d = s_dec + cell * CH;

        float best = d[8 + NB + 0];
        int bi = 0;
#pragma unroll
        for (int c = 1; c < NC; c++) {
            float v = d[8 + NB + c];
            if (v > best) { best = v; bi = c; }
        }
        mylab = (unsigned char)(bi + 1);

        myconf = d[8 + bb];
        valid = myconf > 0.5f;
        float sx = d[bb * 4 + 0];
        float sy = d[bb * 4 + 1];
        float w = d[bb * 4 + 2];
        float h = d[bb * 4 + 3];
        float cx = (sx + (float)gx) / 7.0f;
        float cy = (sy + (float)gy) / 7.0f;
        mybox.x = cx - w / 2.0f;
        mybox.y = cy - h / 2.0f;
        mybox.z = cx + w / 2.0f;
        mybox.w = cy + h / 2.0f;

        int n = b * PER_BATCH + tid;
        g_box[n] = mybox;
        float keyf = valid ? myconf : __int_as_float(0xff800000);   // -inf
        mykey = ((u64)f2sortable(keyf) << 32) | (unsigned)n;
        s_key[tid] = mykey;
    }
    unsigned wb = __ballot_sync(0xffffffffu, valid);
    if ((tid & 31) == 0 && tid < 128) s_wb[tid >> 5] = wb;
    __syncthreads();
    if (tid == 0) {
        u64 m0 = (u64)s_wb[0] | ((u64)s_wb[1] << 32);
        u64 m1 = (u64)s_wb[2] | ((u64)s_wb[3] << 32);
        g_vmask[2 * b] = m0;
        g_vmask[2 * b + 1] = m1;
        int cnt = __popcll(m0) + __popcll(m1);
        s_cnt = cnt;
        g_cnt[b] = cnt;
        s_base = atomicAdd(&g_vtotal, cnt);
    }
    __syncthreads();

    // Phase 2: parallel local rank (valid keys outrank all invalid; keys unique)
    if (tid < PER_BATCH && valid) {
        int r = 0;
#pragma unroll 7
        for (int j = 0; j < PER_BATCH; j++)
            r += (s_key[j] > mykey);
        s_nbox[r] = mybox;
        s_nlab[r] = mylab;
        s_nloc[r] = (unsigned char)tid;
        g_vkeys[s_base + r] = mykey;
    }
    __syncthreads();

    int cnt = s_cnt;

    // Phase 3: flattened triangular pairwise IoU -> adjacency bits
    {
        int P = cnt * (cnt - 1) / 2;
        for (int pp = tid; pp < P; pp += 256) {
            int s = P - 1 - pp;
            int k = (int)floorf((sqrtf(8.0f * (float)s + 1.0f) - 1.0f) * 0.5f);
            while ((k + 1) * (k + 2) / 2 <= s) k++;
            while (k * (k + 1) / 2 > s) k--;
            int o = s - k * (k + 1) / 2;
            int i = cnt - 2 - k;
            int j = cnt - 1 - o;
            if (s_nlab[i] == s_nlab[j]) {
                float4 bi = s_nbox[i];
                float4 bj = s_nbox[j];
                float ltx = fmaxf(bi.x, bj.x);
                float lty = fmaxf(bi.y, bj.y);
                float rbx = fminf(bi.z, bj.z);
                float rby = fminf(bi.w, bj.w);
                float iw = fmaxf(rbx - ltx, 0.0f);
                float ih = fmaxf(rby - lty, 0.0f);
                float inter = iw * ih;
                float ai = (bi.z - bi.x) * (bi.w - bi.y);
                float aj = (bj.z - bj.x) * (bj.w - bj.y);
                float uni = ai + aj - inter;
                float iou = inter / fmaxf(uni, 1e-9f);
                if (iou > THR_NMS)
                    atomicOr(&s_adj[i][j >> 5], 1u << (j & 31));
            }
        }
    }
    __syncthreads();

    // Phase 4: greedy scan, warp-parallel, branch-free mask accumulation
    if (tid < 32) {
        int lane = tid;
        unsigned r00 = s_adj[lane][0],      r01 = s_adj[lane][1];
        unsigned r02 = s_adj[lane][2],      r03 = s_adj[lane][3];
        unsigned r10 = s_adj[lane + 32][0], r11 = s_adj[lane + 32][1];
        unsigned r12 = s_adj[lane + 32][2], r13 = s_adj[lane + 32][3];
        unsigned r20 = s_adj[lane + 64][0], r21 = s_adj[lane + 64][1];
        unsigned r22 = s_adj[lane + 64][2], r23 = s_adj[lane + 64][3];
        unsigned r30 = 0, r31 = 0, r32 = 0, r33 = 0;
        if (lane < 2) {
            r30 = s_adj[lane + 96][0]; r31 = s_adj[lane + 96][1];
            r32 = s_adj[lane + 96][2]; r33 = s_adj[lane + 96][3];
        }

        unsigned sup0 = 0, sup1 = 0, sup2 = 0, sup3 = 0;
        int c = cnt;
        int e0 = min(c, 32);
        for (int s = 0; s < e0; s++) {
            unsigned m = ((sup0 >> s) & 1u) - 1u;      // ~0 if kept, 0 if suppressed
            sup0 |= __shfl_sync(0xffffffffu, r00, s) & m;
            sup1 |= __shfl_sync(0xffffffffu, r01, s) & m;
            sup2 |= __shfl_sync(0xffffffffu, r02, s) & m;
            sup3 |= __shfl_sync(0xffffffffu, r03, s) & m;
        }
        int e1 = min(c - 32, 32);
        for (int s = 0; s < e1; s++) {
            unsigned m = ((sup1 >> s) & 1u) - 1u;
            sup0 |= __shfl_sync(0xffffffffu, r10, s) & m;
            sup1 |= __shfl_sync(0xffffffffu, r11, s) & m;
            sup2 |= __shfl_sync(0xffffffffu, r12, s) & m;
            sup3 |= __shfl_sync(0xffffffffu, r13, s) & m;
        }
        int e2 = min(c - 64, 32);
        for (int s = 0; s < e2; s++) {
            unsigned m = ((sup2 >> s) & 1u) - 1u;
            sup0 |= __shfl_sync(0xffffffffu, r20, s) & m;
            sup1 |= __shfl_sync(0xffffffffu, r21, s) & m;
            sup2 |= __shfl_sync(0xffffffffu, r22, s) & m;
            sup3 |= __shfl_sync(0xffffffffu, r23, s) & m;
        }
        int e3 = min(c - 96, 32);
        for (int s = 0; s < e3; s++) {
            unsigned m = ((sup3 >> s) & 1u) - 1u;
            sup0 |= __shfl_sync(0xffffffffu, r30, s) & m;
            sup1 |= __shfl_sync(0xffffffffu, r31, s) & m;
            sup2 |= __shfl_sync(0xffffffffu, r32, s) & m;
            sup3 |= __shfl_sync(0xffffffffu, r33, s) & m;
        }
        if (lane == 0) {
            s_supw[0] = sup0; s_supw[1] = sup1; s_supw[2] = sup2; s_supw[3] = sup3;
        }
    }
    __syncthreads();

    if (tid < cnt) {
        if (!((s_supw[tid >> 5] >> (tid & 31)) & 1u))
            s_keep[s_nloc[tid]] = 1;
    }
    __syncthreads();

    // Phase 5: payload write
    if (tid < PER_BATCH) {
        int n = b * PER_BATCH + tid;
        g_pay[n] = make_float4(myconf, (float)mylab,
                               s_keep[tid] ? 1.0f : 0.0f, 0.0f);
    }
}

// ============ B) fused valid-rank + invalid-write ============================
// blocks [0, NVBLK): 16 elements/block; warp group q (4 warps) streams
// quarter q of the key array; partial counts combined in smem.
// blocks [NVBLK, NVBLK+NIBLK): invalid elements, O(1) rank each
__global__ void __launch_bounds__(RWB) rank_write_kernel(float* __restrict__ out) {
    int blk = blockIdx.x;
    int tid = threadIdx.x;

    if (blk < NVBLK) {
        int V = g_vtotal;
        int eBase = blk * EPB;
        if (eBase >= V) return;
        int wid = tid >> 5;
        int lane = tid & 31;
        int qtr = wid >> 2;                // stream quarter 0..3
        int quad = wid & 3;                // element group within block
        int e0 = eBase + quad * 4;

        __shared__ int s_part[4][EPB];

        u64 mk0 = g_vkeys[min(e0 + 0, V - 1)];
        u64 mk1 = g_vkeys[min(e0 + 1, V - 1)];
        u64 mk2 = g_vkeys[min(e0 + 2, V - 1)];
        u64 mk3 = g_vkeys[min(e0 + 3, V - 1)];

        int nv2 = V >> 1;                  // ulonglong2 count
        int lo = (nv2 * qtr) >> 2;
        int hi = (nv2 * (qtr + 1)) >> 2;

        int c0 = 0, c1 = 0, c2 = 0, c3 = 0;
        const ulonglong2* vk2 = (const ulonglong2*)g_vkeys;
#pragma unroll 4
        for (int i2 = lo + lane; i2 < hi; i2 += 32) {
            ulonglong2 v = vk2[i2];
            c0 += (v.x > mk0) + (v.y > mk0);
            c1 += (v.x > mk1) + (v.y > mk1);
            c2 += (v.x > mk2) + (v.y > mk2);
            c3 += (v.x > mk3) + (v.y > mk3);
        }
        if ((V & 1) && qtr == 3 && lane == 0) {   // odd tail key
            u64 v = g_vkeys[V - 1];
            c0 += (v > mk0); c1 += (v > mk1); c2 += (v > mk2); c3 += (v > mk3);
        }
#pragma unroll
        for (int d = 16; d >= 1; d >>= 1) {
            c0 += __shfl_xor_sync(0xffffffffu, c0, d);
            c1 += __shfl_xor_sync(0xffffffffu, c1, d);
            c2 += __shfl_xor_sync(0xffffffffu, c2, d);
            c3 += __shfl_xor_sync(0xffffffffu, c3, d);
        }
        if (lane == 0) {
            s_part[qtr][quad * 4 + 0] = c0;
            s_part[qtr][quad * 4 + 1] = c1;
            s_part[qtr][quad * 4 + 2] = c2;
            s_part[qtr][quad * 4 + 3] = c3;
        }
        __syncthreads();

        if (tid < EPB && eBase + tid < V) {
            int rank = s_part[0][tid] + s_part[1][tid]
                     + s_part[2][tid] + s_part[3][tid];
            u64 mykey = g_vkeys[eBase + tid];
            unsigned idx = (unsigned)(mykey & 0xffffffffu);
            float4 bx = g_box[idx];
            float4 pay = g_pay[idx];
            out[rank] = (float)(idx / PER_BATCH);
            *(float4*)(out + NTOT + 4 * rank) = bx;
            out[5 * NTOT + rank] = pay.y;   // label
            out[6 * NTOT + rank] = pay.x;   // score
            out[7 * NTOT + rank] = pay.z;   // keep
        }
    } else {
        __shared__ int s_incl[BATCHN];
        __shared__ int s_ws[4];
        int lane = tid & 31;

        if (tid < BATCHN) {
            int x = g_cnt[tid];
#pragma unroll
            for (int d = 1; d < 32; d <<= 1) {
                int y = __shfl_up_sync(0xffffffffu, x, d);
                if (lane >= d) x += y;
            }
            if (lane == 31) s_ws[tid >> 5] = x;
            s_incl[tid] = x;
        }
        __syncthreads();
        if (tid == 0) {
            int a = 0;
#pragma unroll
            for (int w = 0; w < 4; w++) { int t = s_ws[w]; s_ws[w] = a; a += t; }
        }
        __syncthreads();
        if (tid < BATCHN) s_incl[tid] += s_ws[tid >> 5];
        __syncthreads();

        int V = s_incl[BATCHN - 1];
        int n = (blk - NVBLK) * RWB + tid;
        if (n >= NTOT) return;
        int b = n / PER_BATCH;
        int local = n - b * PER_BATCH;
        u64 m0 = g_vmask[2 * b];
        u64 m1 = g_vmask[2 * b + 1];
        bool valid = (local < 64) ? ((m0 >> local) & 1ULL)
                                  : ((m1 >> (local - 64)) & 1ULL);
        if (valid) return;

        u64 i0 = ~m0;
        u64 i1 = (~m1) & ((1ULL << (PER_BATCH - 64)) - 1);
        int after;
        if (local < 64) {
            u64 hi = (local == 63) ? 0ULL : (i0 >> (local + 1));
            after = __popcll(hi) + __popcll(i1);
        } else {
            after = __popcll(i1 >> (local - 63));
        }
        int invafter = (NTOT - V) - (PER_BATCH * (b + 1) - s_incl[b]);
        int rank = V + invafter + after;

        float4 bx = g_box[n];
        float4 pay = g_pay[n];
        out[rank] = (float)b;
        *(float4*)(out + NTOT + 4 * rank) = bx;
        out[5 * NTOT + rank] = pay.y;
        out[6 * NTOT + rank] = pay.x;
        out[7 * NTOT + rank] = 0.0f;
    }
}

// ---------------- launch -----------------------------------------------------
extern "C" void kernel_launch(void* const* d_in, const int* in_sizes, int n_in,
                              void* d_out, int out_size) {
    const float* p = (const float*)d_in[0];
    float* out = (float*)d_out;

    void* vt = nullptr;
    cudaGetSymbolAddress(&vt, g_vtotal);
    cudaMemsetAsync(vt, 0, sizeof(int));

    decode_nms_kernel<<<BATCHN, 256>>>(p);
    rank_write_kernel<<<NVBLK + NIBLK, RWB>>>(out);
}

// round 13
// speedup vs baseline: 1.8356x; 1.0649x over previous
#include <cuda_runtime.h>
#include <cstdint>

// Problem constants
#define BATCHN 128
#define GS 7
#define NB 2
#define NC 20
#define CH 30
#define CELLS (BATCHN * GS * GS)      // 6272
#define NTOT (CELLS * NB)             // 12544
#define PER_BATCH (GS * GS * NB)      // 98
#define THR_NMS 0.3f

// rank kernel: 512-thread blocks, 16 warps; 16 elements/block;
// warp group q (4 warps) streams quarter q of the key array, 4 elements/warp
#define RWB 512
#define EPB 16
#define NVBLK (NTOT / EPB)            // 784 valid blocks (worst case V = NTOT)
#define NIBLK ((NTOT + RWB - 1) / RWB) // 25 invalid blocks

typedef unsigned long long u64;

// ---------------- device scratch (static; no cudaMalloc) ---------------------
__device__ __align__(16) u64 g_vkeys[NTOT];   // compacted valid keys (any order)
__device__ float4 g_box[NTOT];
__device__ float4 g_pay[NTOT];        // (score, label, keep, 0)
__device__ int g_cnt[BATCHN];         // valid count per batch
__device__ u64 g_vmask[BATCHN * 2];   // validity bitmask per batch (98 bits)
// self-cleaning compaction counter: kernel A adds V total; rank kernel's first
// invalid block subtracts V. Invariant: == 0 before every kernel A launch.
__device__ int g_vtotal;

// sigmoid matching XLA-GPU exp-based logistic: 1/(1+__nv_expf(-x)), div.rn
__device__ __forceinline__ float sigmoidf(float x) {
    return 1.0f / (1.0f + expf(-x));
}

__device__ __forceinline__ unsigned f2sortable(float f) {
    unsigned b = __float_as_uint(f);
    return (b & 0x80000000u) ? ~b : (b | 0x80000000u);
}

// ============ A) fused decode + parallel local rank + NMS + compaction =======
__global__ void __launch_bounds__(256) decode_nms_kernel(const float* __restrict__ p) {
    __shared__ float s_dec[GS * GS * CH];        // 1470 decoded values
    __shared__ u64 s_key[PER_BATCH];
    __shared__ float4 s_nbox[PER_BATCH];
    __shared__ unsigned char s_nlab[PER_BATCH];
    __shared__ unsigned char s_nloc[PER_BATCH];
    __shared__ unsigned char s_keep[PER_BATCH];
    __shared__ __align__(16) unsigned s_adj[PER_BATCH][4];  // suppression rows
    __shared__ unsigned s_supw[4];
    __shared__ unsigned s_wb[4];
    __shared__ int s_cnt;
    __shared__ int s_base;

    int tid = threadIdx.x;
    int b = blockIdx.x;

    // Phase 0: cooperative sigmoid decode (w,h channels raw)
    const float* pb = p + (size_t)b * (GS * GS * CH);
    for (int i = tid; i < GS * GS * CH; i += 256) {
        int c = i % CH;
        float x = pb[i];
        bool raw = (c == 2) | (c == 3) | (c == 6) | (c == 7);
        s_dec[i] = raw ? x : sigmoidf(x);
    }
    if (tid < PER_BATCH) {
        s_adj[tid][0] = 0; s_adj[tid][1] = 0; s_adj[tid][2] = 0; s_adj[tid][3] = 0;
        s_keep[tid] = 0;
    }
    __syncthreads();

    // Phase 1: per-box decode (one thread per box)
    bool valid = false;
    u64 mykey = 0;
    float4 mybox;
    float myconf = 0.0f;
    unsigned char mylab = 0;
    if (tid < PER_BATCH) {
        int cell = tid >> 1;
        int bb = tid & 1;
        int gy = cell / GS, gx = cell % GS;
        const float* d = s_dec + cell * CH;

        float best = d[8 + NB + 0];
        int bi = 0;
#pragma unroll
        for (int c = 1; c < NC; c++) {
            float v = d[8 + NB + c];
            if (v > best) { best = v; bi = c; }
        }
        mylab = (unsigned char)(bi + 1);

        myconf = d[8 + bb];
        valid = myconf > 0.5f;
        float sx = d[bb * 4 + 0];
        float sy = d[bb * 4 + 1];
        float w = d[bb * 4 + 2];
        float h = d[bb * 4 + 3];
        float cx = (sx + (float)gx) / 7.0f;
        float cy = (sy + (float)gy) / 7.0f;
        mybox.x = cx - w / 2.0f;
        mybox.y = cy - h / 2.0f;
        mybox.z = cx + w / 2.0f;
        mybox.w = cy + h / 2.0f;

        int n = b * PER_BATCH + tid;
        g_box[n] = mybox;
        float keyf = valid ? myconf : __int_as_float(0xff800000);   // -inf
        mykey = ((u64)f2sortable(keyf) << 32) | (unsigned)n;
        s_key[tid] = mykey;
    }
    unsigned wb = __ballot_sync(0xffffffffu, valid);
    if ((tid & 31) == 0 && tid < 128) s_wb[tid >> 5] = wb;
    __syncthreads();
    if (tid == 0) {
        u64 m0 = (u64)s_wb[0] | ((u64)s_wb[1] << 32);
        u64 m1 = (u64)s_wb[2] | ((u64)s_wb[3] << 32);
        g_vmask[2 * b] = m0;
        g_vmask[2 * b + 1] = m1;
        int cnt = __popcll(m0) + __popcll(m1);
        s_cnt = cnt;
        g_cnt[b] = cnt;
        s_base = atomicAdd(&g_vtotal, cnt);
    }
    __syncthreads();

    // Phase 2: parallel local rank (valid keys outrank all invalid; keys unique)
    if (tid < PER_BATCH && valid) {
        int r = 0;
#pragma unroll 7
        for (int j = 0; j < PER_BATCH; j++)
            r += (s_key[j] > mykey);
        s_nbox[r] = mybox;
        s_nlab[r] = mylab;
        s_nloc[r] = (unsigned char)tid;
        g_vkeys[s_base + r] = mykey;
    }
    __syncthreads();

    int cnt = s_cnt;

    // Phase 3: flattened triangular pairwise IoU -> adjacency bits
    {
        int P = cnt * (cnt - 1) / 2;
        for (int pp = tid; pp < P; pp += 256) {
            int s = P - 1 - pp;
            int k = (int)floorf((sqrtf(8.0f * (float)s + 1.0f) - 1.0f) * 0.5f);
            while ((k + 1) * (k + 2) / 2 <= s) k++;
            while (k * (k + 1) / 2 > s) k--;
            int o = s - k * (k + 1) / 2;
            int i = cnt - 2 - k;
            int j = cnt - 1 - o;
            if (s_nlab[i] == s_nlab[j]) {
                float4 bi = s_nbox[i];
                float4 bj = s_nbox[j];
                float ltx = fmaxf(bi.x, bj.x);
                float lty = fmaxf(bi.y, bj.y);
                float rbx = fminf(bi.z, bj.z);
                float rby = fminf(bi.w, bj.w);
                float iw = fmaxf(rbx - ltx, 0.0f);
                float ih = fmaxf(rby - lty, 0.0f);
                float inter = iw * ih;
                float ai = (bi.z - bi.x) * (bi.w - bi.y);
                float aj = (bj.z - bj.x) * (bj.w - bj.y);
                float uni = ai + aj - inter;
                float iou = inter / fmaxf(uni, 1e-9f);
                if (iou > THR_NMS)
                    atomicOr(&s_adj[i][j >> 5], 1u << (j & 31));
            }
        }
    }
    __syncthreads();

    // Phase 4: greedy scan, warp-parallel, branch-free mask accumulation
    if (tid < 32) {
        int lane = tid;
        unsigned r00 = s_adj[lane][0],      r01 = s_adj[lane][1];
        unsigned r02 = s_adj[lane][2],      r03 = s_adj[lane][3];
        unsigned r10 = s_adj[lane + 32][0], r11 = s_adj[lane + 32][1];
        unsigned r12 = s_adj[lane + 32][2], r13 = s_adj[lane + 32][3];
        unsigned r20 = s_adj[lane + 64][0], r21 = s_adj[lane + 64][1];
        unsigned r22 = s_adj[lane + 64][2], r23 = s_adj[lane + 64][3];
        unsigned r30 = 0, r31 = 0, r32 = 0, r33 = 0;
        if (lane < 2) {
            r30 = s_adj[lane + 96][0]; r31 = s_adj[lane + 96][1];
            r32 = s_adj[lane + 96][2]; r33 = s_adj[lane + 96][3];
        }

        unsigned sup0 = 0, sup1 = 0, sup2 = 0, sup3 = 0;
        int c = cnt;
        int e0 = min(c, 32);
        for (int s = 0; s < e0; s++) {
            unsigned m = ((sup0 >> s) & 1u) - 1u;      // ~0 if kept, 0 if suppressed
            sup0 |= __shfl_sync(0xffffffffu, r00, s) & m;
            sup1 |= __shfl_sync(0xffffffffu, r01, s) & m;
            sup2 |= __shfl_sync(0xffffffffu, r02, s) & m;
            sup3 |= __shfl_sync(0xffffffffu, r03, s) & m;
        }
        int e1 = min(c - 32, 32);
        for (int s = 0; s < e1; s++) {
            unsigned m = ((sup1 >> s) & 1u) - 1u;
            sup0 |= __shfl_sync(0xffffffffu, r10, s) & m;
            sup1 |= __shfl_sync(0xffffffffu, r11, s) & m;
            sup2 |= __shfl_sync(0xffffffffu, r12, s) & m;
            sup3 |= __shfl_sync(0xffffffffu, r13, s) & m;
        }
        int e2 = min(c - 64, 32);
        for (int s = 0; s < e2; s++) {
            unsigned m = ((sup2 >> s) & 1u) - 1u;
            sup0 |= __shfl_sync(0xffffffffu, r20, s) & m;
            sup1 |= __shfl_sync(0xffffffffu, r21, s) & m;
            sup2 |= __shfl_sync(0xffffffffu, r22, s) & m;
            sup3 |= __shfl_sync(0xffffffffu, r23, s) & m;
        }
        int e3 = min(c - 96, 32);
        for (int s = 0; s < e3; s++) {
            unsigned m = ((sup3 >> s) & 1u) - 1u;
            sup0 |= __shfl_sync(0xffffffffu, r30, s) & m;
            sup1 |= __shfl_sync(0xffffffffu, r31, s) & m;
            sup2 |= __shfl_sync(0xffffffffu, r32, s) & m;
            sup3 |= __shfl_sync(0xffffffffu, r33, s) & m;
        }
        if (lane == 0) {
            s_supw[0] = sup0; s_supw[1] = sup1; s_supw[2] = sup2; s_supw[3] = sup3;
        }
    }
    __syncthreads();

    if (tid < cnt) {
        if (!((s_supw[tid >> 5] >> (tid & 31)) & 1u))
            s_keep[s_nloc[tid]] = 1;
    }
    __syncthreads();

    // Phase 5: payload write
    if (tid < PER_BATCH) {
        int n = b * PER_BATCH + tid;
        g_pay[n] = make_float4(myconf, (float)mylab,
                               s_keep[tid] ? 1.0f : 0.0f, 0.0f);
    }
}

// ============ B) fused valid-rank + invalid-write ============================
// blocks [0, NVBLK): 16 elements/block; warp group q (4 warps) streams
// quarter q of the key array with 4-deep load batching (MLP=4).
// blocks [NVBLK, NVBLK+NIBLK): invalid elements, O(1) rank each; the first
// invalid block also restores the self-cleaning counter invariant.
__global__ void __launch_bounds__(RWB, 3) rank_write_kernel(float* __restrict__ out) {
    int blk = blockIdx.x;
    int tid = threadIdx.x;

    if (blk < NVBLK) {
        __shared__ int s_part[4][EPB];
        __shared__ int s_V;

        // V = sum of per-batch valid counts (no dependence on g_vtotal)
        if (tid < 32) {
            int s = g_cnt[tid] + g_cnt[tid + 32] + g_cnt[tid + 64] + g_cnt[tid + 96];
#pragma unroll
            for (int d = 16; d >= 1; d >>= 1)
                s += __shfl_xor_sync(0xffffffffu, s, d);
            if (tid == 0) s_V = s;
        }
        __syncthreads();
        int V = s_V;

        int eBase = blk * EPB;
        if (eBase >= V) return;
        int wid = tid >> 5;
        int lane = tid & 31;
        int qtr = wid >> 2;                // stream quarter 0..3
        int quad = wid & 3;                // element group within block
        int e0 = eBase + quad * 4;

        u64 mk0 = g_vkeys[min(e0 + 0, V - 1)];
        u64 mk1 = g_vkeys[min(e0 + 1, V - 1)];
        u64 mk2 = g_vkeys[min(e0 + 2, V - 1)];
        u64 mk3 = g_vkeys[min(e0 + 3, V - 1)];

        int nv2 = V >> 1;                  // ulonglong2 count
        int lo = (nv2 * qtr) >> 2;
        int hi = (nv2 * (qtr + 1)) >> 2;

        int c0 = 0, c1 = 0, c2 = 0, c3 = 0;
        const ulonglong2* vk2 = (const ulonglong2*)g_vkeys;
        int i2 = lo + lane;
        // main loop: 4 loads in flight, 32 compares per iteration
#pragma unroll 1
        for (; i2 + 96 < hi; i2 += 128) {
            ulonglong2 va = vk2[i2];
            ulonglong2 vb = vk2[i2 + 32];
            ulonglong2 vc = vk2[i2 + 64];
            ulonglong2 vd = vk2[i2 + 96];
            c0 += (va.x > mk0) + (va.y > mk0) + (vb.x > mk0) + (vb.y > mk0)
                + (vc.x > mk0) + (vc.y > mk0) + (vd.x > mk0) + (vd.y > mk0);
            c1 += (va.x > mk1) + (va.y > mk1) + (vb.x > mk1) + (vb.y > mk1)
                + (vc.x > mk1) + (vc.y > mk1) + (vd.x > mk1) + (vd.y > mk1);
            c2 += (va.x > mk2) + (va.y > mk2) + (vb.x > mk2) + (vb.y > mk2)
                + (vc.x > mk2) + (vc.y > mk2) + (vd.x > mk2) + (vd.y > mk2);
            c3 += (va.x > mk3) + (va.y > mk3) + (vb.x > mk3) + (vb.y > mk3)
                + (vc.x > mk3) + (vc.y > mk3) + (vd.x > mk3) + (vd.y > mk3);
        }
#pragma unroll 1
        for (; i2 < hi; i2 += 32) {
            ulonglong2 v = vk2[i2];
            c0 += (v.x > mk0) + (v.y > mk0);
            c1 += (v.x > mk1) + (v.y > mk1);
            c2 += (v.x > mk2) + (v.y > mk2);
            c3 += (v.x > mk3) + (v.y > mk3);
        }
        if ((V & 1) && qtr == 3 && lane == 0) {   // odd tail key
            u64 v = g_vkeys[V - 1];
            c0 += (v > mk0); c1 += (v > mk1); c2 += (v > mk2); c3 += (v > mk3);
        }
#pragma unroll
        for (int d = 16; d >= 1; d >>= 1) {
            c0 += __shfl_xor_sync(0xffffffffu, c0, d);
            c1 += __shfl_xor_sync(0xffffffffu, c1, d);
            c2 += __shfl_xor_sync(0xffffffffu, c2, d);
            c3 += __shfl_xor_sync(0xffffffffu, c3, d);
        }
        if (lane == 0) {
            s_part[qtr][quad * 4 + 0] = c0;
            s_part[qtr][quad * 4 + 1] = c1;
            s_part[qtr][quad * 4 + 2] = c2;
            s_part[qtr][quad * 4 + 3] = c3;
        }
        __syncthreads();

        if (tid < EPB && eBase + tid < V) {
            int rank = s_part[0][tid] + s_part[1][tid]
                     + s_part[2][tid] + s_part[3][tid];
            u64 mykey = g_vkeys[eBase + tid];
            unsigned idx = (unsigned)(mykey & 0xffffffffu);
            float4 bx = g_box[idx];
            float4 pay = g_pay[idx];
            out[rank] = (float)(idx / PER_BATCH);
            *(float4*)(out + NTOT + 4 * rank) = bx;
            out[5 * NTOT + rank] = pay.y;   // label
            out[6 * NTOT + rank] = pay.x;   // score
            out[7 * NTOT + rank] = pay.z;   // keep
        }
    } else {
        __shared__ int s_incl[BATCHN];
        __shared__ int s_ws[4];
        int lane = tid & 31;

        if (tid < BATCHN) {
            int x = g_cnt[tid];
#pragma unroll
            for (int d = 1; d < 32; d <<= 1) {
                int y = __shfl_up_sync(0xffffffffu, x, d);
                if (lane >= d) x += y;
            }
            if (lane == 31) s_ws[tid >> 5] = x;
            s_incl[tid] = x;
        }
        __syncthreads();
        if (tid == 0) {
            int a = 0;
#pragma unroll
            for (int w = 0; w < 4; w++) { int t = s_ws[w]; s_ws[w] = a; a += t; }
        }
        __syncthreads();
        if (tid < BATCHN) s_incl[tid] += s_ws[tid >> 5];
        __syncthreads();

        int V = s_incl[BATCHN - 1];
        // restore counter invariant for the next launch (kernel ordering
        // guarantees all of kernel A's adds precede this, and the next
        // launch's adds follow it)
        if (blk == NVBLK && tid == 0) atomicSub(&g_vtotal, V);

        int n = (blk - NVBLK) * RWB + tid;
        if (n >= NTOT) return;
        int b = n / PER_BATCH;
        int local = n - b * PER_BATCH;
        u64 m0 = g_vmask[2 * b];
        u64 m1 = g_vmask[2 * b + 1];
        bool valid = (local < 64) ? ((m0 >> local) & 1ULL)
                                  : ((m1 >> (local - 64)) & 1ULL);
        if (valid) return;

        u64 i0 = ~m0;
        u64 i1 = (~m1) & ((1ULL << (PER_BATCH - 64)) - 1);
        int after;
        if (local < 64) {
            u64 hi = (local == 63) ? 0ULL : (i0 >> (local + 1));
            after = __popcll(hi) + __popcll(i1);
        } else {
            after = __popcll(i1 >> (local - 63));
        }
        int invafter = (NTOT - V) - (PER_BATCH * (b + 1) - s_incl[b]);
        int rank = V + invafter + after;

        float4 bx = g_box[n];
        float4 pay = g_pay[n];
        out[rank] = (float)b;
        *(float4*)(out + NTOT + 4 * rank) = bx;
        out[5 * NTOT + rank] = pay.y;
        out[6 * NTOT + rank] = pay.x;
        out[7 * NTOT + rank] = 0.0f;
    }
}

// ---------------- launch -----------------------------------------------------
extern "C" void kernel_launch(void* const* d_in, const int* in_sizes, int n_in,
                              void* d_out, int out_size) {
    const float* p = (const float*)d_in[0];
    float* out = (float*)d_out;

    decode_nms_kernel<<<BATCHN, 256>>>(p);
    rank_write_kernel<<<NVBLK + NIBLK, RWB>>>(out);
}